// round 10
// baseline (speedup 1.0000x reference)
#include <cuda_runtime.h>
#include <cstdint>

#define IN_DIM 128
#define OUT_DIM 128
#define MAX_NODES 50000
#define MAX_EDGES 800000

// Static scratch (no allocations allowed)
__device__ int   g_degcnt[MAX_NODES];     // count of col==i
__device__ int   g_rowcnt[MAX_NODES];     // count of row==i
__device__ int   g_rowfill[MAX_NODES];    // fill cursor, seeded to rowptr[i]
__device__ int   g_rowptr[MAX_NODES + 1]; // CSR offsets
__device__ int   g_cs[MAX_EDGES];         // CSR col indices (bucketed by row)
__device__ float g_dinv[MAX_NODES];
__device__ float g_h[(size_t)MAX_NODES * OUT_DIM];

// ---------------------------------------------------------------------------
// Init: zero counters (graph replays -> must rerun every launch)
// ---------------------------------------------------------------------------
__global__ void k_init(int n) {
    int i = blockIdx.x * blockDim.x + threadIdx.x;
    if (i < n) {
        g_degcnt[i] = 0;
        g_rowcnt[i] = 0;
    }
}

// ---------------------------------------------------------------------------
// Histogram: per-row counts (CSR) and per-col counts (degree).
// int32 indices, 2 edges/thread via int2.
// ---------------------------------------------------------------------------
__global__ void k_count(const int* __restrict__ row,
                        const int* __restrict__ col, int E2, int E) {
    int i = blockIdx.x * blockDim.x + threadIdx.x;
    if (i < E2) {
        int2 r = ((const int2*)row)[i];
        int2 c = ((const int2*)col)[i];
        atomicAdd(&g_rowcnt[r.x], 1);
        atomicAdd(&g_rowcnt[r.y], 1);
        atomicAdd(&g_degcnt[c.x], 1);
        atomicAdd(&g_degcnt[c.y], 1);
    } else {
        int j = E2 * 2 + (i - E2);   // tail (E odd)
        if (j < E) {
            atomicAdd(&g_rowcnt[row[j]], 1);
            atomicAdd(&g_degcnt[col[j]], 1);
        }
    }
}

// ---------------------------------------------------------------------------
// Exclusive scan of g_rowcnt -> g_rowptr, single block, shuffle-based.
// Also seeds g_rowfill[i] = rowptr[i] (fill cursor) and computes dinv.
// ---------------------------------------------------------------------------
__global__ void __launch_bounds__(1024) k_scan_dinv(int n) {
    __shared__ int warp_sums[32];
    const int tid   = threadIdx.x;
    const int lane  = tid & 31;
    const int wid   = tid >> 5;
    const int CHUNK = (n + 1023) / 1024;
    const int s = tid * CHUNK;
    const int e = (s + CHUNK < n) ? s + CHUNK : n;

    int sum = 0;
    for (int i = s; i < e; i++) sum += g_rowcnt[i];

    int v = sum;
#pragma unroll
    for (int o = 1; o < 32; o <<= 1) {
        int t = __shfl_up_sync(0xFFFFFFFFu, v, o);
        if (lane >= o) v += t;
    }
    if (lane == 31) warp_sums[wid] = v;
    __syncthreads();
    if (wid == 0) {
        int wv = warp_sums[lane];
#pragma unroll
        for (int o = 1; o < 32; o <<= 1) {
            int t = __shfl_up_sync(0xFFFFFFFFu, wv, o);
            if (lane >= o) wv += t;
        }
        warp_sums[lane] = wv;
    }
    __syncthreads();
    int excl = v - sum + (wid > 0 ? warp_sums[wid - 1] : 0);

    if (tid == 0) g_rowptr[0] = 0;
    int run = excl;
    for (int i = s; i < e; i++) {
        g_rowfill[i] = run;          // fill cursor starts at rowptr[i]
        run += g_rowcnt[i];
        g_rowptr[i + 1] = run;
    }

    for (int i = tid; i < n; i += 1024)
        g_dinv[i] = rsqrtf(1.0f + (float)g_degcnt[i]);
}

// ---------------------------------------------------------------------------
// Fill CSR: g_cs[atomicAdd(&g_rowfill[r],1)] = col   (cursor pre-seeded)
// ---------------------------------------------------------------------------
__global__ void k_fill(const int* __restrict__ row,
                       const int* __restrict__ col, int E2, int E) {
    int i = blockIdx.x * blockDim.x + threadIdx.x;
    if (i < E2) {
        int2 r = ((const int2*)row)[i];
        int2 c = ((const int2*)col)[i];
        g_cs[atomicAdd(&g_rowfill[r.x], 1)] = c.x;
        g_cs[atomicAdd(&g_rowfill[r.y], 1)] = c.y;
    } else {
        int j = E2 * 2 + (i - E2);
        if (j < E)
            g_cs[atomicAdd(&g_rowfill[row[j]], 1)] = col[j];
    }
}

// ---------------------------------------------------------------------------
// GEMM: h[m][n] = sum_k x[m][k] * W[n][k]
// BM=64, BN=128, BK=16; 256 threads; 4x8 thread tile; double-buffered smem.
// Epilogue: g_h = h;  out = dinv[m]^2 * h   (self-loop term init)
// ---------------------------------------------------------------------------
__global__ void __launch_bounds__(256) k_gemm(const float* __restrict__ x,
                                              const float* __restrict__ W,
                                              float* __restrict__ out,
                                              int n_nodes) {
    __shared__ float As[2][16][64];
    __shared__ float Bs[2][16][128];

    const int tid = threadIdx.x;
    const int bm  = blockIdx.x * 64;
    const int tx  = tid & 15;
    const int ty  = tid >> 4;

    float acc[4][8];
#pragma unroll
    for (int i = 0; i < 4; i++)
#pragma unroll
        for (int j = 0; j < 8; j++) acc[i][j] = 0.0f;

    const int lm = tid >> 2;
    const int lk = (tid & 3) * 4;
    const int wn = tid >> 1;
    const int wk = (tid & 1) * 8;
    const int m_ld = bm + lm;
    const bool m_ok = (m_ld < n_nodes);

    // prologue: load tile 0 into buffer 0
    float4 xv = make_float4(0.f, 0.f, 0.f, 0.f);
    if (m_ok) xv = *(const float4*)(x + (size_t)m_ld * IN_DIM + lk);
    float4 w0 = *(const float4*)(W + (size_t)wn * IN_DIM + wk);
    float4 w1 = *(const float4*)(W + (size_t)wn * IN_DIM + wk + 4);
    As[0][lk + 0][lm] = xv.x; As[0][lk + 1][lm] = xv.y;
    As[0][lk + 2][lm] = xv.z; As[0][lk + 3][lm] = xv.w;
    Bs[0][wk + 0][wn] = w0.x; Bs[0][wk + 1][wn] = w0.y;
    Bs[0][wk + 2][wn] = w0.z; Bs[0][wk + 3][wn] = w0.w;
    Bs[0][wk + 4][wn] = w1.x; Bs[0][wk + 5][wn] = w1.y;
    Bs[0][wk + 6][wn] = w1.z; Bs[0][wk + 7][wn] = w1.w;
    __syncthreads();

#pragma unroll
    for (int it = 0; it < IN_DIM / 16; it++) {
        const int cur = it & 1;
        const int nxt = cur ^ 1;
        // prefetch next tile into registers (latency overlapped with compute)
        if (it < IN_DIM / 16 - 1) {
            int kc = (it + 1) * 16;
            xv = make_float4(0.f, 0.f, 0.f, 0.f);
            if (m_ok) xv = *(const float4*)(x + (size_t)m_ld * IN_DIM + kc + lk);
            w0 = *(const float4*)(W + (size_t)wn * IN_DIM + kc + wk);
            w1 = *(const float4*)(W + (size_t)wn * IN_DIM + kc + wk + 4);
        }

#pragma unroll
        for (int k = 0; k < 16; k++) {
            float4 a  = ((const float4*)As[cur][k])[ty];
            float4 b0 = ((const float4*)Bs[cur][k])[tx * 2];
            float4 b1 = ((const float4*)Bs[cur][k])[tx * 2 + 1];
            float av[4] = {a.x, a.y, a.z, a.w};
            float bv[8] = {b0.x, b0.y, b0.z, b0.w, b1.x, b1.y, b1.z, b1.w};
#pragma unroll
            for (int i = 0; i < 4; i++)
#pragma unroll
                for (int j = 0; j < 8; j++) acc[i][j] += av[i] * bv[j];
        }

        if (it < IN_DIM / 16 - 1) {
            As[nxt][lk + 0][lm] = xv.x; As[nxt][lk + 1][lm] = xv.y;
            As[nxt][lk + 2][lm] = xv.z; As[nxt][lk + 3][lm] = xv.w;
            Bs[nxt][wk + 0][wn] = w0.x; Bs[nxt][wk + 1][wn] = w0.y;
            Bs[nxt][wk + 2][wn] = w0.z; Bs[nxt][wk + 3][wn] = w0.w;
            Bs[nxt][wk + 4][wn] = w1.x; Bs[nxt][wk + 5][wn] = w1.y;
            Bs[nxt][wk + 6][wn] = w1.z; Bs[nxt][wk + 7][wn] = w1.w;
            __syncthreads();
        }
    }

#pragma unroll
    for (int i = 0; i < 4; i++) {
        int m = bm + ty * 4 + i;
        if (m >= n_nodes) continue;
        float di  = g_dinv[m];
        float di2 = di * di;
        float4 h0 = make_float4(acc[i][0], acc[i][1], acc[i][2], acc[i][3]);
        float4 h1 = make_float4(acc[i][4], acc[i][5], acc[i][6], acc[i][7]);
        float4 o0 = make_float4(h0.x * di2, h0.y * di2, h0.z * di2, h0.w * di2);
        float4 o1 = make_float4(h1.x * di2, h1.y * di2, h1.z * di2, h1.w * di2);
        size_t base = (size_t)m * OUT_DIM + tx * 8;
        *(float4*)(g_h + base)     = h0;
        *(float4*)(g_h + base + 4) = h1;
        *(float4*)(out + base)     = o0;
        *(float4*)(out + base + 4) = o1;
    }
}

// ---------------------------------------------------------------------------
// Aggregate: one warp per node (owner-computes, no atomics), 8-edge unroll
// out[i] = relu( out[i] + sum_{e in row i} dinv[i]*dinv[col] * h[col] )
// ---------------------------------------------------------------------------
__global__ void __launch_bounds__(256) k_agg(float* __restrict__ out, int n) {
    int w    = (blockIdx.x * blockDim.x + threadIdx.x) >> 5;
    int lane = threadIdx.x & 31;
    if (w >= n) return;

    int s = g_rowptr[w];
    int e = g_rowptr[w + 1];
    float di = g_dinv[w];

    float* op = out + (size_t)w * OUT_DIM + lane * 4;
    float4 acc = *(float4*)op;  // self-loop term from GEMM epilogue

    int j = s;
    for (; j + 7 < e; j += 8) {
        int   c[8];
        float wt[8];
        float4 hv[8];
#pragma unroll
        for (int u = 0; u < 8; u++) c[u] = g_cs[j + u];
#pragma unroll
        for (int u = 0; u < 8; u++) wt[u] = di * g_dinv[c[u]];
#pragma unroll
        for (int u = 0; u < 8; u++)
            hv[u] = *(const float4*)(g_h + (size_t)c[u] * OUT_DIM + lane * 4);
#pragma unroll
        for (int u = 0; u < 8; u++) {
            acc.x += wt[u] * hv[u].x;
            acc.y += wt[u] * hv[u].y;
            acc.z += wt[u] * hv[u].z;
            acc.w += wt[u] * hv[u].w;
        }
    }
    for (; j < e; j++) {
        int cc = g_cs[j];
        float wv = di * g_dinv[cc];
        float4 hv = *(const float4*)(g_h + (size_t)cc * OUT_DIM + lane * 4);
        acc.x += wv * hv.x;
        acc.y += wv * hv.y;
        acc.z += wv * hv.z;
        acc.w += wv * hv.w;
    }

    acc.x = fmaxf(acc.x, 0.f);
    acc.y = fmaxf(acc.y, 0.f);
    acc.z = fmaxf(acc.z, 0.f);
    acc.w = fmaxf(acc.w, 0.f);
    *(float4*)op = acc;
}

// ---------------------------------------------------------------------------
extern "C" void kernel_launch(void* const* d_in, const int* in_sizes, int n_in,
                              void* d_out, int out_size) {
    const float* x  = (const float*)d_in[0];
    const float* W  = (const float*)d_in[1];
    const int*   ei = (const int*)d_in[2];   // int32 (JAX x64 disabled)
    float* out = (float*)d_out;

    const int n_nodes = in_sizes[0] / IN_DIM;
    const int E       = in_sizes[2] / 2;
    const int E2      = E / 2;               // int2 pairs
    const int* row = ei;
    const int* col = ei + E;

    int cnt_threads = E2 + (E - E2 * 2 > 0 ? (E - E2 * 2) : 0) + 1;

    k_init     <<<(n_nodes + 255) / 256, 256>>>(n_nodes);
    k_count    <<<(cnt_threads + 255) / 256, 256>>>(row, col, E2, E);
    k_scan_dinv<<<1, 1024>>>(n_nodes);
    k_fill     <<<(cnt_threads + 255) / 256, 256>>>(row, col, E2, E);
    k_gemm     <<<(n_nodes + 63) / 64, 256>>>(x, W, out, n_nodes);

    int warps_per_block = 256 / 32;
    int agg_blocks = (n_nodes + warps_per_block - 1) / warps_per_block;
    k_agg      <<<agg_blocks, 256>>>(out, n_nodes);
}